// round 5
// baseline (speedup 1.0000x reference)
#include <cuda_runtime.h>
#include <cuda_fp16.h>
#include <cstdint>

// ---------------------------------------------------------------------------
// y[m,n] = (sum_k x[m,k] * sign[n,k]) * scale[n] + bias[n]
//   M = 8192 (B*S), N = 4096, K = 4096, fp32 in gmem.
//
// Harness compiles at virtual arch compute_103 (no 'a' suffix) -> tcgen05 PTX
// is unavailable. Use baseline PTX only: cp.async + ldmatrix + mma.sync
// (m16n8k16 f16 -> f32 accum). fp32->fp16 pre-convert into __device__ scratch.
// ---------------------------------------------------------------------------

#define M_TOTAL 8192
#define N_TOTAL 4096
#define K_TOTAL 4096

#define BM 128
#define BN 128
#define BK 64
#define STAGES 4
#define KSTAGES (K_TOTAL / BK)            // 64

#define STAGE_A_BYTES (BM * BK * 2)        // 16384
#define STAGE_B_BYTES (BN * BK * 2)        // 16384
#define STAGE_BYTES   (STAGE_A_BYTES + STAGE_B_BYTES)   // 32768
#define SMEM_TOTAL    (STAGES * STAGE_BYTES)            // 131072

// fp16 scratch (module-static device memory; no runtime allocation)
__device__ __align__(1024) __half g_xh[(size_t)M_TOTAL * K_TOTAL];
__device__ __align__(1024) __half g_sh[(size_t)N_TOTAL * K_TOTAL];

// ---------------------------------------------------------------------------
__device__ __forceinline__ uint32_t smem_u32(const void* p) {
    uint32_t a;
    asm("{ .reg .u64 t; cvta.to.shared.u64 t, %1; cvt.u32.u64 %0, t; }"
        : "=r"(a) : "l"(p));
    return a;
}

__device__ __forceinline__ void cp_async16(uint32_t dst, const void* src) {
    asm volatile("cp.async.cg.shared.global [%0], [%1], 16;"
                 :: "r"(dst), "l"(src) : "memory");
}
__device__ __forceinline__ void cp_commit() {
    asm volatile("cp.async.commit_group;" ::: "memory");
}
template <int N>
__device__ __forceinline__ void cp_wait() {
    asm volatile("cp.async.wait_group %0;" :: "n"(N) : "memory");
}

__device__ __forceinline__ void ldsm4(uint32_t* r, uint32_t addr) {
    asm volatile("ldmatrix.sync.aligned.m8n8.x4.shared.b16 {%0,%1,%2,%3}, [%4];"
                 : "=r"(r[0]), "=r"(r[1]), "=r"(r[2]), "=r"(r[3]) : "r"(addr));
}

__device__ __forceinline__ void mma16816(float* c, const uint32_t* a,
                                         uint32_t b0, uint32_t b1) {
    asm volatile(
        "mma.sync.aligned.m16n8k16.row.col.f32.f16.f16.f32 "
        "{%0,%1,%2,%3}, {%4,%5,%6,%7}, {%8,%9}, {%0,%1,%2,%3};"
        : "+f"(c[0]), "+f"(c[1]), "+f"(c[2]), "+f"(c[3])
        : "r"(a[0]), "r"(a[1]), "r"(a[2]), "r"(a[3]), "r"(b0), "r"(b1));
}

// ---------------------------------------------------------------------------
// fp32 -> fp16 conversion (vectorized)
// ---------------------------------------------------------------------------
__global__ void cvt_f32_to_f16(const float4* __restrict__ src,
                               uint2* __restrict__ dst, int n4) {
    int i = blockIdx.x * blockDim.x + threadIdx.x;
    if (i >= n4) return;
    float4 v = src[i];
    __half2 h0 = __floats2half2_rn(v.x, v.y);
    __half2 h1 = __floats2half2_rn(v.z, v.w);
    uint2 o;
    o.x = *reinterpret_cast<const unsigned int*>(&h0);
    o.y = *reinterpret_cast<const unsigned int*>(&h1);
    dst[i] = o;
}

// ---------------------------------------------------------------------------
// GEMM: CTA 128x128, K staged 64, 4-stage cp.async pipeline, 8 warps (2x4),
// warp tile 64x32, mma.m16n8k16. SW128 swizzle applied by hand.
// Smem tiles: As[128 rows(m)][64 k] and Bs[128 rows(n)][64 k], 128B rows.
// ---------------------------------------------------------------------------
__global__ __launch_bounds__(256, 1) void sign_gemm_kernel(
    const __half* __restrict__ xh,
    const __half* __restrict__ sh,
    const float* __restrict__ scale,
    const float* __restrict__ bias,
    float* __restrict__ out)
{
    extern __shared__ __align__(1024) char smem[];
    const uint32_t sbase = smem_u32(smem);
    const int tid = threadIdx.x;
    const int lane = tid & 31;
    const int wid = tid >> 5;
    const int warp_m = wid >> 2;     // 0..1 -> m offset 0/64
    const int warp_n = wid & 3;      // 0..3 -> n offset 0/32/64/96

    const int m0 = blockIdx.y * BM;
    const int n0 = blockIdx.x * BN;

    // ---- loader: 2048 x 16B chunks per stage (1024 A + 1024 B), 256 threads
    // chunk c = tid + i*256: row = c>>3 (0..127), kc = c&7 (16B column chunk)
    auto issue_stage = [&](int ks) {
        const int slot = ks & (STAGES - 1);
        const uint32_t sA = sbase + slot * STAGE_BYTES;
        const uint32_t sB = sA + STAGE_A_BYTES;
        #pragma unroll
        for (int i = 0; i < 4; i++) {
            int c = tid + i * 256;
            int row = c >> 3;
            int kc = c & 7;
            uint32_t d = (uint32_t)row * 128 + ((kc * 16) ^ ((row & 7) * 16));
            const __half* srcA = xh + (size_t)(m0 + row) * K_TOTAL + ks * BK + kc * 8;
            const __half* srcB = sh + (size_t)(n0 + row) * K_TOTAL + ks * BK + kc * 8;
            cp_async16(sA + d, srcA);
            cp_async16(sB + d, srcB);
        }
        cp_commit();
    };

    // ---- ldmatrix per-thread address components (swizzle mask constant/lane)
    const uint32_t swz = (uint32_t)(lane & 7) * 16;
    const uint32_t a_row_off =
        (uint32_t)(warp_m * 64 + (lane & 7) + ((lane >> 3) & 1) * 8) * 128;
    const uint32_t a_col0 = ((lane >> 4) & 1) * 16;
    const uint32_t b_row_off =
        (uint32_t)(warp_n * 32 + (lane & 7) + ((lane >> 4) & 1) * 8) * 128;
    const uint32_t b_col0 = ((lane >> 3) & 1) * 16;

    float acc[4][4][4];
    #pragma unroll
    for (int i = 0; i < 4; i++)
        #pragma unroll
        for (int j = 0; j < 4; j++)
            #pragma unroll
            for (int k = 0; k < 4; k++) acc[i][j][k] = 0.f;

    // prologue: fill STAGES-1 stages
    #pragma unroll
    for (int s = 0; s < STAGES - 1; s++) issue_stage(s);

    for (int ks = 0; ks < KSTAGES; ks++) {
        cp_wait<STAGES - 2>();
        __syncthreads();

        // refill the slot freed by the previous iteration
        if (ks + STAGES - 1 < KSTAGES) issue_stage(ks + STAGES - 1);

        const int slot = ks & (STAGES - 1);
        const uint32_t sA = sbase + slot * STAGE_BYTES;
        const uint32_t sB = sA + STAGE_A_BYTES;

        #pragma unroll
        for (int kk = 0; kk < 4; kk++) {            // 4 x k16
            uint32_t a[4][4];
            uint32_t b[2][4];
            #pragma unroll
            for (int mi = 0; mi < 4; mi++)
                ldsm4(a[mi], sA + a_row_off + (uint32_t)mi * (16 * 128) +
                             (((uint32_t)kk * 32 + a_col0) ^ swz));
            #pragma unroll
            for (int jj = 0; jj < 2; jj++)
                ldsm4(b[jj], sB + b_row_off + (uint32_t)jj * (16 * 128) +
                             (((uint32_t)kk * 32 + b_col0) ^ swz));
            #pragma unroll
            for (int mi = 0; mi < 4; mi++)
                #pragma unroll
                for (int ni = 0; ni < 4; ni++)
                    mma16816(acc[mi][ni], a[mi],
                             b[ni >> 1][(ni & 1) * 2],
                             b[ni >> 1][(ni & 1) * 2 + 1]);
        }
    }

    // ---- epilogue: scale/bias + float2 stores
    const int g = lane >> 2;      // row within 8-block
    const int tig = lane & 3;     // col pair
    float sc0[4], sc1[4], bi0[4], bi1[4];
    #pragma unroll
    for (int ni = 0; ni < 4; ni++) {
        int n = n0 + warp_n * 32 + ni * 8 + tig * 2;
        sc0[ni] = __ldg(scale + n);
        sc1[ni] = __ldg(scale + n + 1);
        bi0[ni] = __ldg(bias + n);
        bi1[ni] = __ldg(bias + n + 1);
    }
    #pragma unroll
    for (int mi = 0; mi < 4; mi++) {
        int m = m0 + warp_m * 64 + mi * 16 + g;
        #pragma unroll
        for (int ni = 0; ni < 4; ni++) {
            int n = n0 + warp_n * 32 + ni * 8 + tig * 2;
            float2 v0, v1;
            v0.x = acc[mi][ni][0] * sc0[ni] + bi0[ni];
            v0.y = acc[mi][ni][1] * sc1[ni] + bi1[ni];
            v1.x = acc[mi][ni][2] * sc0[ni] + bi0[ni];
            v1.y = acc[mi][ni][3] * sc1[ni] + bi1[ni];
            *reinterpret_cast<float2*>(out + (size_t)m * N_TOTAL + n) = v0;
            *reinterpret_cast<float2*>(out + (size_t)(m + 8) * N_TOTAL + n) = v1;
        }
    }
}

// ---------------------------------------------------------------------------
// Host launcher
// ---------------------------------------------------------------------------
extern "C" void kernel_launch(void* const* d_in, const int* in_sizes, int n_in,
                              void* d_out, int out_size) {
    const float* x    = (const float*)d_in[0];
    const float* sgn  = (const float*)d_in[1];
    const float* scal = (const float*)d_in[2];
    const float* bias = (const float*)d_in[3];
    float* out        = (float*)d_out;

    void* xh_ptr = nullptr;
    void* sh_ptr = nullptr;
    cudaGetSymbolAddress(&xh_ptr, g_xh);
    cudaGetSymbolAddress(&sh_ptr, g_sh);

    // 1) fp32 -> fp16 conversion passes
    const int nx4 = (M_TOTAL * K_TOTAL) / 4;
    const int ns4 = (N_TOTAL * K_TOTAL) / 4;
    cvt_f32_to_f16<<<(nx4 + 255) / 256, 256>>>((const float4*)x,   (uint2*)xh_ptr, nx4);
    cvt_f32_to_f16<<<(ns4 + 255) / 256, 256>>>((const float4*)sgn, (uint2*)sh_ptr, ns4);

    // 2) GEMM (n-major grid: fp16 sign panel stays L2-resident across waves)
    cudaFuncSetAttribute(sign_gemm_kernel,
                         cudaFuncAttributeMaxDynamicSharedMemorySize, SMEM_TOTAL);
    dim3 grid(N_TOTAL / BN, M_TOTAL / BM);   // (32, 64)
    sign_gemm_kernel<<<grid, 256, SMEM_TOTAL>>>(
        (const __half*)xh_ptr, (const __half*)sh_ptr, scal, bias, out);
}

// round 6
// speedup vs baseline: 1.1322x; 1.1322x over previous
#include <cuda_runtime.h>
#include <cuda_fp16.h>
#include <cstdint>

// ---------------------------------------------------------------------------
// y[m,n] = (sum_k x[m,k] * sign[n,k]) * scale[n] + bias[n]
//   M = 8192 (B*S), N = 4096, K = 4096, fp32 in gmem.
//
// compute_103 virtual arch -> no tcgen05; baseline PTX only:
// cp.async + ldmatrix + mma.sync.m16n8k16 (f16 in, f32 accum).
// R5 measured 788us with CTA 128x128 / warp 64x32: smem crossbar bound
// (125 B/cyc needed vs 128 B/cyc). This round: CTA 128x256, warp tile 64x64
// -> 86 B/cyc smem, HMMA-bound.
// ---------------------------------------------------------------------------

#define M_TOTAL 8192
#define N_TOTAL 4096
#define K_TOTAL 4096

#define BM 128
#define BN 256
#define BK 64
#define STAGES 4
#define KSTAGES (K_TOTAL / BK)            // 64

#define STAGE_A_BYTES (BM * BK * 2)        // 16384
#define STAGE_B_BYTES (BN * BK * 2)        // 32768
#define STAGE_BYTES   (STAGE_A_BYTES + STAGE_B_BYTES)   // 49152
#define SMEM_TOTAL    (STAGES * STAGE_BYTES)            // 196608

// fp16 scratch (module-static device memory; no runtime allocation)
__device__ __align__(1024) __half g_xh[(size_t)M_TOTAL * K_TOTAL];
__device__ __align__(1024) __half g_sh[(size_t)N_TOTAL * K_TOTAL];

// ---------------------------------------------------------------------------
__device__ __forceinline__ uint32_t smem_u32(const void* p) {
    uint32_t a;
    asm("{ .reg .u64 t; cvta.to.shared.u64 t, %1; cvt.u32.u64 %0, t; }"
        : "=r"(a) : "l"(p));
    return a;
}

__device__ __forceinline__ void cp_async16(uint32_t dst, const void* src) {
    asm volatile("cp.async.cg.shared.global [%0], [%1], 16;"
                 :: "r"(dst), "l"(src) : "memory");
}
__device__ __forceinline__ void cp_commit() {
    asm volatile("cp.async.commit_group;" ::: "memory");
}
template <int N>
__device__ __forceinline__ void cp_wait() {
    asm volatile("cp.async.wait_group %0;" :: "n"(N) : "memory");
}

__device__ __forceinline__ void ldsm4(uint32_t* r, uint32_t addr) {
    asm volatile("ldmatrix.sync.aligned.m8n8.x4.shared.b16 {%0,%1,%2,%3}, [%4];"
                 : "=r"(r[0]), "=r"(r[1]), "=r"(r[2]), "=r"(r[3]) : "r"(addr));
}

__device__ __forceinline__ void mma16816(float* c, const uint32_t* a,
                                         uint32_t b0, uint32_t b1) {
    asm volatile(
        "mma.sync.aligned.m16n8k16.row.col.f32.f16.f16.f32 "
        "{%0,%1,%2,%3}, {%4,%5,%6,%7}, {%8,%9}, {%0,%1,%2,%3};"
        : "+f"(c[0]), "+f"(c[1]), "+f"(c[2]), "+f"(c[3])
        : "r"(a[0]), "r"(a[1]), "r"(a[2]), "r"(a[3]), "r"(b0), "r"(b1));
}

// ---------------------------------------------------------------------------
// fp32 -> fp16 conversion (vectorized)
// ---------------------------------------------------------------------------
__global__ void cvt_f32_to_f16(const float4* __restrict__ src,
                               uint2* __restrict__ dst, int n4) {
    int i = blockIdx.x * blockDim.x + threadIdx.x;
    if (i >= n4) return;
    float4 v = src[i];
    __half2 h0 = __floats2half2_rn(v.x, v.y);
    __half2 h1 = __floats2half2_rn(v.z, v.w);
    uint2 o;
    o.x = *reinterpret_cast<const unsigned int*>(&h0);
    o.y = *reinterpret_cast<const unsigned int*>(&h1);
    dst[i] = o;
}

// ---------------------------------------------------------------------------
// GEMM: CTA 128x256, K staged 64, 4-stage cp.async pipeline, 8 warps (2x4),
// warp tile 64x64, mma.m16n8k16. SW128 swizzle applied by hand.
// Smem: As[128 m][64 k], Bs[256 n][64 k], 128B rows, per stage.
// ---------------------------------------------------------------------------
__global__ __launch_bounds__(256, 1) void sign_gemm_kernel(
    const __half* __restrict__ xh,
    const __half* __restrict__ sh,
    const float* __restrict__ scale,
    const float* __restrict__ bias,
    float* __restrict__ out)
{
    extern __shared__ __align__(1024) char smem[];
    const uint32_t sbase = smem_u32(smem);
    const int tid = threadIdx.x;
    const int lane = tid & 31;
    const int wid = tid >> 5;
    const int warp_m = wid >> 2;     // 0..1 -> m offset 0/64
    const int warp_n = wid & 3;      // 0..3 -> n offset 0/64/128/192

    const int m0 = blockIdx.y * BM;
    const int n0 = blockIdx.x * BN;

    // ---- loader: per stage 1024 A-chunks + 2048 B-chunks of 16B, 256 thr
    auto issue_stage = [&](int ks) {
        const int slot = ks & (STAGES - 1);
        const uint32_t sA = sbase + slot * STAGE_BYTES;
        const uint32_t sB = sA + STAGE_A_BYTES;
        #pragma unroll
        for (int i = 0; i < 4; i++) {            // A: chunks 0..1023
            int c = tid + i * 256;
            int row = c >> 3;
            int kc = c & 7;
            uint32_t d = (uint32_t)row * 128 + ((kc * 16) ^ ((row & 7) * 16));
            cp_async16(sA + d, xh + (size_t)(m0 + row) * K_TOTAL + ks * BK + kc * 8);
        }
        #pragma unroll
        for (int i = 0; i < 8; i++) {            // B: chunks 0..2047
            int c = tid + i * 256;
            int row = c >> 3;
            int kc = c & 7;
            uint32_t d = (uint32_t)row * 128 + ((kc * 16) ^ ((row & 7) * 16));
            cp_async16(sB + d, sh + (size_t)(n0 + row) * K_TOTAL + ks * BK + kc * 8);
        }
        cp_commit();
    };

    // ---- ldmatrix per-thread address components
    const uint32_t swz = (uint32_t)(lane & 7) * 16;
    const uint32_t a_row_off =
        (uint32_t)(warp_m * 64 + (lane & 7) + ((lane >> 3) & 1) * 8) * 128;
    const uint32_t a_col0 = ((lane >> 4) & 1) * 16;
    const uint32_t b_row_off =
        (uint32_t)(warp_n * 64 + (lane & 7) + ((lane >> 4) & 1) * 8) * 128;
    const uint32_t b_col0 = ((lane >> 3) & 1) * 16;

    float acc[4][8][4];
    #pragma unroll
    for (int i = 0; i < 4; i++)
        #pragma unroll
        for (int j = 0; j < 8; j++)
            #pragma unroll
            for (int k = 0; k < 4; k++) acc[i][j][k] = 0.f;

    // prologue: fill STAGES-1 stages
    #pragma unroll
    for (int s = 0; s < STAGES - 1; s++) issue_stage(s);

    for (int ks = 0; ks < KSTAGES; ks++) {
        cp_wait<STAGES - 2>();
        __syncthreads();

        // refill the slot freed by the previous iteration
        if (ks + STAGES - 1 < KSTAGES) issue_stage(ks + STAGES - 1);

        const int slot = ks & (STAGES - 1);
        const uint32_t sA = sbase + slot * STAGE_BYTES;
        const uint32_t sB = sA + STAGE_A_BYTES;

        #pragma unroll
        for (int kk = 0; kk < 4; kk++) {            // 4 x k16
            uint32_t a[4][4];
            uint32_t b[4][4];
            #pragma unroll
            for (int mi = 0; mi < 4; mi++)
                ldsm4(a[mi], sA + a_row_off + (uint32_t)mi * (16 * 128) +
                             (((uint32_t)kk * 32 + a_col0) ^ swz));
            #pragma unroll
            for (int jj = 0; jj < 4; jj++)
                ldsm4(b[jj], sB + b_row_off + (uint32_t)jj * (16 * 128) +
                             (((uint32_t)kk * 32 + b_col0) ^ swz));
            #pragma unroll
            for (int mi = 0; mi < 4; mi++)
                #pragma unroll
                for (int ni = 0; ni < 8; ni++)
                    mma16816(acc[mi][ni], a[mi],
                             b[ni >> 1][(ni & 1) * 2],
                             b[ni >> 1][(ni & 1) * 2 + 1]);
        }
    }

    // ---- epilogue: scale/bias + float2 stores
    const int g = lane >> 2;      // row within 8-block
    const int tig = lane & 3;     // col pair
    float sc0[8], sc1[8], bi0[8], bi1[8];
    #pragma unroll
    for (int ni = 0; ni < 8; ni++) {
        int n = n0 + warp_n * 64 + ni * 8 + tig * 2;
        sc0[ni] = __ldg(scale + n);
        sc1[ni] = __ldg(scale + n + 1);
        bi0[ni] = __ldg(bias + n);
        bi1[ni] = __ldg(bias + n + 1);
    }
    #pragma unroll
    for (int mi = 0; mi < 4; mi++) {
        int m = m0 + warp_m * 64 + mi * 16 + g;
        #pragma unroll
        for (int ni = 0; ni < 8; ni++) {
            int n = n0 + warp_n * 64 + ni * 8 + tig * 2;
            float2 v0, v1;
            v0.x = acc[mi][ni][0] * sc0[ni] + bi0[ni];
            v0.y = acc[mi][ni][1] * sc1[ni] + bi1[ni];
            v1.x = acc[mi][ni][2] * sc0[ni] + bi0[ni];
            v1.y = acc[mi][ni][3] * sc1[ni] + bi1[ni];
            *reinterpret_cast<float2*>(out + (size_t)m * N_TOTAL + n) = v0;
            *reinterpret_cast<float2*>(out + (size_t)(m + 8) * N_TOTAL + n) = v1;
        }
    }
}

// ---------------------------------------------------------------------------
// Host launcher
// ---------------------------------------------------------------------------
extern "C" void kernel_launch(void* const* d_in, const int* in_sizes, int n_in,
                              void* d_out, int out_size) {
    const float* x    = (const float*)d_in[0];
    const float* sgn  = (const float*)d_in[1];
    const float* scal = (const float*)d_in[2];
    const float* bias = (const float*)d_in[3];
    float* out        = (float*)d_out;

    void* xh_ptr = nullptr;
    void* sh_ptr = nullptr;
    cudaGetSymbolAddress(&xh_ptr, g_xh);
    cudaGetSymbolAddress(&sh_ptr, g_sh);

    // 1) fp32 -> fp16 conversion passes
    const int nx4 = (M_TOTAL * K_TOTAL) / 4;
    const int ns4 = (N_TOTAL * K_TOTAL) / 4;
    cvt_f32_to_f16<<<(nx4 + 255) / 256, 256>>>((const float4*)x,   (uint2*)xh_ptr, nx4);
    cvt_f32_to_f16<<<(ns4 + 255) / 256, 256>>>((const float4*)sgn, (uint2*)sh_ptr, ns4);

    // 2) GEMM (n-major grid: fp16 sign panel stays L2-resident across waves)
    cudaFuncSetAttribute(sign_gemm_kernel,
                         cudaFuncAttributeMaxDynamicSharedMemorySize, SMEM_TOTAL);
    dim3 grid(N_TOTAL / BN, M_TOTAL / BM);   // (16, 64)
    sign_gemm_kernel<<<grid, 256, SMEM_TOTAL>>>(
        (const __half*)xh_ptr, (const __half*)sh_ptr, scal, bias, out);
}

// round 11
// speedup vs baseline: 1.1843x; 1.0461x over previous
#include <cuda_runtime.h>
#include <cuda_fp16.h>
#include <cstdint>

// ---------------------------------------------------------------------------
// y[m,n] = (sum_k x[m,k] * sign[n,k]) * scale[n] + bias[n]
//   M = 8192 (B*S), N = 4096, K = 4096, fp32 in gmem.
//
// compute_103 virtual arch -> no tcgen05; baseline PTX only:
// cp.async + ldmatrix + mma.sync.m16n8k16 (f16 in, f32 accum).
// R5: 788us (crossbar-bound, warp 64x32). R6: 696us (warp 64x64, 1 CTA/SM).
// R7: same warp tile, CTA 128x128 / 4 warps / 3 stages (96KB) -> 2 CTAs/SM
// so barrier drain + ldsm ramp at the 64 stage boundaries is hidden by the
// co-resident CTA.
// ---------------------------------------------------------------------------

#define M_TOTAL 8192
#define N_TOTAL 4096
#define K_TOTAL 4096

#define BM 128
#define BN 128
#define BK 64
#define STAGES 3
#define KSTAGES (K_TOTAL / BK)            // 64

#define STAGE_A_BYTES (BM * BK * 2)        // 16384
#define STAGE_B_BYTES (BN * BK * 2)        // 16384
#define STAGE_BYTES   (STAGE_A_BYTES + STAGE_B_BYTES)   // 32768
#define SMEM_TOTAL    (STAGES * STAGE_BYTES)            // 98304 -> 2 CTAs/SM

// fp16 scratch (module-static device memory; no runtime allocation)
__device__ __align__(1024) __half g_xh[(size_t)M_TOTAL * K_TOTAL];
__device__ __align__(1024) __half g_sh[(size_t)N_TOTAL * K_TOTAL];

// ---------------------------------------------------------------------------
__device__ __forceinline__ uint32_t smem_u32(const void* p) {
    uint32_t a;
    asm("{ .reg .u64 t; cvta.to.shared.u64 t, %1; cvt.u32.u64 %0, t; }"
        : "=r"(a) : "l"(p));
    return a;
}

__device__ __forceinline__ void cp_async16(uint32_t dst, const void* src) {
    asm volatile("cp.async.cg.shared.global [%0], [%1], 16;"
                 :: "r"(dst), "l"(src) : "memory");
}
__device__ __forceinline__ void cp_commit() {
    asm volatile("cp.async.commit_group;" ::: "memory");
}
template <int N>
__device__ __forceinline__ void cp_wait() {
    asm volatile("cp.async.wait_group %0;" :: "n"(N) : "memory");
}

__device__ __forceinline__ void ldsm4(uint32_t* r, uint32_t addr) {
    asm volatile("ldmatrix.sync.aligned.m8n8.x4.shared.b16 {%0,%1,%2,%3}, [%4];"
                 : "=r"(r[0]), "=r"(r[1]), "=r"(r[2]), "=r"(r[3]) : "r"(addr));
}

__device__ __forceinline__ void mma16816(float* c, const uint32_t* a,
                                         uint32_t b0, uint32_t b1) {
    asm volatile(
        "mma.sync.aligned.m16n8k16.row.col.f32.f16.f16.f32 "
        "{%0,%1,%2,%3}, {%4,%5,%6,%7}, {%8,%9}, {%0,%1,%2,%3};"
        : "+f"(c[0]), "+f"(c[1]), "+f"(c[2]), "+f"(c[3])
        : "r"(a[0]), "r"(a[1]), "r"(a[2]), "r"(a[3]), "r"(b0), "r"(b1));
}

// ---------------------------------------------------------------------------
// fp32 -> fp16 conversion (vectorized)
// ---------------------------------------------------------------------------
__global__ void cvt_f32_to_f16(const float4* __restrict__ src,
                               uint2* __restrict__ dst, int n4) {
    int i = blockIdx.x * blockDim.x + threadIdx.x;
    if (i >= n4) return;
    float4 v = src[i];
    __half2 h0 = __floats2half2_rn(v.x, v.y);
    __half2 h1 = __floats2half2_rn(v.z, v.w);
    uint2 o;
    o.x = *reinterpret_cast<const unsigned int*>(&h0);
    o.y = *reinterpret_cast<const unsigned int*>(&h1);
    dst[i] = o;
}

// ---------------------------------------------------------------------------
// GEMM: CTA 128x128, 4 warps (2x2), warp tile 64x64, 3-stage cp.async
// pipeline, mma.m16n8k16. SW128 swizzle applied by hand. 2 CTAs/SM.
// ---------------------------------------------------------------------------
__global__ __launch_bounds__(128, 2) void sign_gemm_kernel(
    const __half* __restrict__ xh,
    const __half* __restrict__ sh,
    const float* __restrict__ scale,
    const float* __restrict__ bias,
    float* __restrict__ out)
{
    extern __shared__ __align__(1024) char smem[];
    const uint32_t sbase = smem_u32(smem);
    const int tid = threadIdx.x;
    const int lane = tid & 31;
    const int wid = tid >> 5;
    const int warp_m = wid >> 1;     // 0..1 -> m offset 0/64
    const int warp_n = wid & 1;      // 0..1 -> n offset 0/64

    const int m0 = blockIdx.y * BM;
    const int n0 = blockIdx.x * BN;

    // ---- loader: per stage 1024 A-chunks + 1024 B-chunks of 16B, 128 thr
    auto issue_stage = [&](int ks, int slot) {
        const uint32_t sA = sbase + slot * STAGE_BYTES;
        const uint32_t sB = sA + STAGE_A_BYTES;
        #pragma unroll
        for (int i = 0; i < 8; i++) {
            int c = tid + i * 128;
            int row = c >> 3;
            int kc = c & 7;
            uint32_t d = (uint32_t)row * 128 + ((kc * 16) ^ ((row & 7) * 16));
            cp_async16(sA + d, xh + (size_t)(m0 + row) * K_TOTAL + ks * BK + kc * 8);
            cp_async16(sB + d, sh + (size_t)(n0 + row) * K_TOTAL + ks * BK + kc * 8);
        }
        cp_commit();
    };

    // ---- ldmatrix per-thread address components
    const uint32_t swz = (uint32_t)(lane & 7) * 16;
    const uint32_t a_row_off =
        (uint32_t)(warp_m * 64 + (lane & 7) + ((lane >> 3) & 1) * 8) * 128;
    const uint32_t a_col0 = ((lane >> 4) & 1) * 16;
    const uint32_t b_row_off =
        (uint32_t)(warp_n * 64 + (lane & 7) + ((lane >> 4) & 1) * 8) * 128;
    const uint32_t b_col0 = ((lane >> 3) & 1) * 16;

    float acc[4][8][4];
    #pragma unroll
    for (int i = 0; i < 4; i++)
        #pragma unroll
        for (int j = 0; j < 8; j++)
            #pragma unroll
            for (int k = 0; k < 4; k++) acc[i][j][k] = 0.f;

    // prologue: fill STAGES-1 stages
    issue_stage(0, 0);
    issue_stage(1, 1);

    int slot = 0;           // slot of stage ks
    int fill_slot = 2;      // slot for stage ks+2
    for (int ks = 0; ks < KSTAGES; ks++) {
        cp_wait<STAGES - 2>();
        __syncthreads();

        // refill the slot freed by the previous iteration
        if (ks + STAGES - 1 < KSTAGES) issue_stage(ks + STAGES - 1, fill_slot);

        const uint32_t sA = sbase + slot * STAGE_BYTES;
        const uint32_t sB = sA + STAGE_A_BYTES;

        #pragma unroll
        for (int kk = 0; kk < 4; kk++) {            // 4 x k16
            uint32_t a[4][4];
            uint32_t b[4][4];
            #pragma unroll
            for (int mi = 0; mi < 4; mi++)
                ldsm4(a[mi], sA + a_row_off + (uint32_t)mi * (16 * 128) +
                             (((uint32_t)kk * 32 + a_col0) ^ swz));
            #pragma unroll
            for (int jj = 0; jj < 4; jj++)
                ldsm4(b[jj], sB + b_row_off + (uint32_t)jj * (16 * 128) +
                             (((uint32_t)kk * 32 + b_col0) ^ swz));
            #pragma unroll
            for (int mi = 0; mi < 4; mi++)
                #pragma unroll
                for (int ni = 0; ni < 8; ni++)
                    mma16816(acc[mi][ni], a[mi],
                             b[ni >> 1][(ni & 1) * 2],
                             b[ni >> 1][(ni & 1) * 2 + 1]);
        }

        slot = (slot == STAGES - 1) ? 0 : slot + 1;
        fill_slot = (fill_slot == STAGES - 1) ? 0 : fill_slot + 1;
    }

    // ---- epilogue: scale/bias + float2 stores
    const int g = lane >> 2;      // row within 8-block
    const int tig = lane & 3;     // col pair
    float sc0[8], sc1[8], bi0[8], bi1[8];
    #pragma unroll
    for (int ni = 0; ni < 8; ni++) {
        int n = n0 + warp_n * 64 + ni * 8 + tig * 2;
        sc0[ni] = __ldg(scale + n);
        sc1[ni] = __ldg(scale + n + 1);
        bi0[ni] = __ldg(bias + n);
        bi1[ni] = __ldg(bias + n + 1);
    }
    #pragma unroll
    for (int mi = 0; mi < 4; mi++) {
        int m = m0 + warp_m * 64 + mi * 16 + g;
        #pragma unroll
        for (int ni = 0; ni < 8; ni++) {
            int n = n0 + warp_n * 64 + ni * 8 + tig * 2;
            float2 v0, v1;
            v0.x = acc[mi][ni][0] * sc0[ni] + bi0[ni];
            v0.y = acc[mi][ni][1] * sc1[ni] + bi1[ni];
            v1.x = acc[mi][ni][2] * sc0[ni] + bi0[ni];
            v1.y = acc[mi][ni][3] * sc1[ni] + bi1[ni];
            *reinterpret_cast<float2*>(out + (size_t)m * N_TOTAL + n) = v0;
            *reinterpret_cast<float2*>(out + (size_t)(m + 8) * N_TOTAL + n) = v1;
        }
    }
}

// ---------------------------------------------------------------------------
// Host launcher
// ---------------------------------------------------------------------------
extern "C" void kernel_launch(void* const* d_in, const int* in_sizes, int n_in,
                              void* d_out, int out_size) {
    const float* x    = (const float*)d_in[0];
    const float* sgn  = (const float*)d_in[1];
    const float* scal = (const float*)d_in[2];
    const float* bias = (const float*)d_in[3];
    float* out        = (float*)d_out;

    void* xh_ptr = nullptr;
    void* sh_ptr = nullptr;
    cudaGetSymbolAddress(&xh_ptr, g_xh);
    cudaGetSymbolAddress(&sh_ptr, g_sh);

    // 1) fp32 -> fp16 conversion passes
    const int nx4 = (M_TOTAL * K_TOTAL) / 4;
    const int ns4 = (N_TOTAL * K_TOTAL) / 4;
    cvt_f32_to_f16<<<(nx4 + 255) / 256, 256>>>((const float4*)x,   (uint2*)xh_ptr, nx4);
    cvt_f32_to_f16<<<(ns4 + 255) / 256, 256>>>((const float4*)sgn, (uint2*)sh_ptr, ns4);

    // 2) GEMM (n-major grid: fp16 sign panel stays L2-resident across waves)
    cudaFuncSetAttribute(sign_gemm_kernel,
                         cudaFuncAttributeMaxDynamicSharedMemorySize, SMEM_TOTAL);
    dim3 grid(N_TOTAL / BN, M_TOTAL / BM);   // (32, 64)
    sign_gemm_kernel<<<grid, 128, SMEM_TOTAL>>>(
        (const __half*)xh_ptr, (const __half*)sh_ptr, scal, bias, out);
}